// round 14
// baseline (speedup 1.0000x reference)
#include <cuda_runtime.h>
#include <cuda_bf16.h>
#include <stdint.h>

#define NT 8192
#define TK 2
#define NE 8
#define DM 1024
#define DF 2048
#define CAP 3072
#define TB 8192u            // tile bytes: 128 rows x 32 K-cols bf16, SW64-swizzled
#define IDESC1 0x8200490u   // kind::f16: F32 acc, bf16 A/B, M=128, N=128
#define IDESC2 0x8400490u   // N=256 variant

#if defined(__CUDA_ARCH__) && (__CUDA_ARCH__ >= 1000) && \
    (defined(__CUDA_ARCH_FEAT_SM103_ALL) || defined(__CUDA_ARCH_FEAT_SM100_ALL) || \
     defined(__CUDA_ARCH_FEAT_SM101_ALL) || defined(__CUDA_ARCH_SPECIFIC__) || \
     defined(__CUDA_ARCH_FAMILY_SPECIFIC__))
#define TC 1
#else
#define TC 0
#endif

// ---- persistent scratch (8KB SW64 tiles) ----
// A: ((e*24+m128)*32+k32)   W1/W2: ((e*16+n128)*32+k32)
// W3: ((e*8+n128)*64+k32)   H: ((e*24+m128)*64+f32)
__device__ int   g_cnt[NE];
__device__ int   g_tok[NE * CAP];
__device__ float g_wt[NE * CAP];
__device__ __align__(128) __nv_bfloat16 g_ah[(size_t)NE*CAP*DM], g_al[(size_t)NE*CAP*DM];
__device__ __align__(128) __nv_bfloat16 g_w1h[(size_t)NE*DF*DM], g_w1l[(size_t)NE*DF*DM];
__device__ __align__(128) __nv_bfloat16 g_w2h[(size_t)NE*DF*DM], g_w2l[(size_t)NE*DF*DM];
__device__ __align__(128) __nv_bfloat16 g_w3h[(size_t)NE*DM*DF], g_w3l[(size_t)NE*DM*DF];
__device__ __align__(128) __nv_bfloat16 g_hh[(size_t)NE*CAP*DF], g_hl[(size_t)NE*CAP*DF];

// ---- helpers ----
__device__ __forceinline__ uint32_t smem_u32(const void* p) {
    uint32_t a;
    asm("{ .reg .u64 t; cvta.to.shared.u64 t, %1; cvt.u32.u64 %0, t; }" : "=r"(a) : "l"(p));
    return a;
}
__device__ __forceinline__ uint32_t pk(float hi, float lo) {
    uint32_t r; asm("cvt.rn.bf16x2.f32 %0, %1, %2;" : "=r"(r) : "f"(hi), "f"(lo)); return r;
}
__device__ __forceinline__ void red2(float* p, float a, float b) {
    asm volatile("red.global.add.v2.f32 [%0], {%1, %2};" :: "l"(p), "f"(a), "f"(b) : "memory");
}
__device__ __forceinline__ uint32_t swz64(uint32_t o) { return o ^ ((o >> 3) & 0x30); }

#if TC
__device__ __forceinline__ uint64_t sdesc(uint32_t a) {  // K-major SW64: LBO=1, SBO=32
    return ((uint64_t)4 << 61) | ((uint64_t)1 << 46) | ((uint64_t)32 << 32) |
           ((uint64_t)1 << 16) | ((a >> 4) & 0x3FFF);
}
__device__ __forceinline__ void mma_ss(uint32_t d, uint64_t ad, uint64_t bd,
                                       uint32_t idesc, uint32_t en) {
    asm volatile(
        "{\n\t.reg .pred p;\n\tsetp.ne.u32 p, %4, 0;\n\t"
        "tcgen05.mma.cta_group::1.kind::f16 [%0], %1, %2, %3, {%5, %5, %5, %5}, p;\n\t}"
        :: "r"(d), "l"(ad), "l"(bd), "r"(idesc), "r"(en), "r"(0u) : "memory");
}
__device__ __forceinline__ void mwait(uint32_t mbar, int phase) {
    asm volatile(
        "{\n\t.reg .pred P;\n\tWL%=:\n\t"
        "mbarrier.try_wait.parity.acquire.cta.shared::cta.b64 P, [%0], %1, 0x989680;\n\t"
        "@P bra.uni WD%=;\n\tbra.uni WL%=;\n\tWD%=:\n\t}"
        :: "r"(mbar), "r"((uint32_t)phase) : "memory");
}
__device__ __forceinline__ void bulkcp(uint32_t dst, const void* src, uint32_t mbar) {
    asm volatile(
        "cp.async.bulk.shared::cluster.global.mbarrier::complete_tx::bytes [%0], [%1], %2, [%3];"
        :: "r"(dst), "l"(src), "r"(TB), "r"(mbar) : "memory");
}
__device__ __forceinline__ void expect_tx(uint32_t mbar, uint32_t bytes) {
    asm volatile("mbarrier.arrive.expect_tx.shared.b64 _, [%0], %1;"
                 :: "r"(mbar), "r"(bytes) : "memory");
}
__device__ __forceinline__ void mbinit(uint32_t mbar) {
    asm volatile("mbarrier.init.shared.b64 [%0], 1;" :: "r"(mbar) : "memory");
}
__device__ __forceinline__ void commit_to(uint32_t mbar) {
    asm volatile("tcgen05.commit.cta_group::1.mbarrier::arrive::one.shared::cluster.b64 [%0];"
                 :: "r"(mbar) : "memory");
}
#define LDTM32(r, addr) \
    asm volatile("tcgen05.ld.sync.aligned.32x32b.x32.b32 " \
        "{%0,%1,%2,%3,%4,%5,%6,%7,%8,%9,%10,%11,%12,%13,%14,%15," \
        "%16,%17,%18,%19,%20,%21,%22,%23,%24,%25,%26,%27,%28,%29,%30,%31}, [%32];" \
        : "=r"((r)[0]),"=r"((r)[1]),"=r"((r)[2]),"=r"((r)[3]),"=r"((r)[4]),"=r"((r)[5]), \
          "=r"((r)[6]),"=r"((r)[7]),"=r"((r)[8]),"=r"((r)[9]),"=r"((r)[10]),"=r"((r)[11]), \
          "=r"((r)[12]),"=r"((r)[13]),"=r"((r)[14]),"=r"((r)[15]),"=r"((r)[16]),"=r"((r)[17]), \
          "=r"((r)[18]),"=r"((r)[19]),"=r"((r)[20]),"=r"((r)[21]),"=r"((r)[22]),"=r"((r)[23]), \
          "=r"((r)[24]),"=r"((r)[25]),"=r"((r)[26]),"=r"((r)[27]),"=r"((r)[28]),"=r"((r)[29]), \
          "=r"((r)[30]),"=r"((r)[31]) : "r"(addr))
#endif  // TC

// ---- dispatch / prep ----
__global__ void k_zero() { if (threadIdx.x < NE) g_cnt[threadIdx.x] = 0; }

__global__ void k_dispatch(const int* __restrict__ idx, const float* __restrict__ w) {
    int i = blockIdx.x * blockDim.x + threadIdx.x;
    if (i >= NT * TK) return;
    int e = idx[i];
    int p = atomicAdd(&g_cnt[e], 1);
    if (p < CAP) { g_tok[e * CAP + p] = i >> 1; g_wt[e * CAP + p] = w[i]; }
}

__global__ void k_gather(const float* __restrict__ x) {
    int e = blockIdx.y, r = blockIdx.x;
    if (r >= min(g_cnt[e], CAP)) return;
    int t = g_tok[e * CAP + r];
    int d = threadIdx.x * 4;
    float4 v = *(const float4*)(x + (size_t)t * DM + d);
    float f0 = __bfloat162float(__float2bfloat16(v.x));
    float f1 = __bfloat162float(__float2bfloat16(v.y));
    float f2 = __bfloat162float(__float2bfloat16(v.z));
    float f3 = __bfloat162float(__float2bfloat16(v.w));
    size_t tile = (size_t)((e * 24 + (r >> 7)) * 32 + (d >> 5)) * TB;
    uint32_t off = swz64((uint32_t)(r & 127) * 64 + (d & 31) * 2);
    *(uint2*)((char*)g_ah + tile + off) = make_uint2(pk(f1, f0), pk(f3, f2));
    *(uint2*)((char*)g_al + tile + off) = make_uint2(pk(v.y - f1, v.x - f0), pk(v.w - f3, v.z - f2));
}

// transpose + split: src [E][K][N] f32 -> SW64 tiles [E][n128][k32]
__global__ __launch_bounds__(256) void k_transw(const float* __restrict__ src,
                                                int which, int K, int N) {
    __shared__ float ts[32][33];
    __nv_bfloat16 *dh, *dl;
    if (which == 0)      { dh = g_w1h; dl = g_w1l; }
    else if (which == 1) { dh = g_w2h; dl = g_w2l; }
    else                 { dh = g_w3h; dl = g_w3l; }
    const int KB = K / 32;
    int e = blockIdx.z, n0 = blockIdx.x * 32, k0 = blockIdx.y * 32;
    int tx = threadIdx.x & 31, ty = threadIdx.x >> 5;
    const float* s = src + (size_t)e * K * N;
#pragma unroll
    for (int j = 0; j < 4; j++) ts[ty + 8 * j][tx] = s[(size_t)(k0 + ty + 8 * j) * N + n0 + tx];
    __syncthreads();
    int tilesPerE = (N / 128) * KB;
#pragma unroll
    for (int j = 0; j < 4; j++) {
        int n = n0 + ty + 8 * j, k = k0 + tx;
        float v = ts[tx][ty + 8 * j];
        size_t tile = (size_t)(e * tilesPerE + (n >> 7) * KB + (k >> 5)) * TB;
        uint32_t off = swz64((uint32_t)(n & 127) * 64 + (k & 31) * 2);
        __nv_bfloat16 h = __float2bfloat16(v);
        *(__nv_bfloat16*)((char*)dh + tile + off) = h;
        *(__nv_bfloat16*)((char*)dl + tile + off) = __float2bfloat16(v - __bfloat162float(h));
    }
}

// ==================== GEMM1: M=256, N=128, K32 stages, 3-ring ====================
// stage: a0h a0l a1h a1l b1h b1l b2h b2l (8 x 8KB). TMEM: gm0@0 vm0@128 gm1@256 vm1@384
__global__ __launch_bounds__(256) void k_gemm1_tc() {
#if TC
    extern __shared__ char sm[];
    const int e = blockIdx.z, mb = blockIdx.y, nb = blockIdx.x;
    int cnt = min(g_cnt[e], CAP);
    if (mb * 256 >= cnt) return;
    const int tid = threadIdx.x;
    uint32_t sb = smem_u32(sm);
    if ((tid >> 5) == 0)
        asm volatile("tcgen05.alloc.cta_group::1.sync.aligned.shared::cta.b32 [%0], %1;"
                     :: "r"(sb + 48), "r"(512) : "memory");
    if (tid == 0) {
#pragma unroll
        for (int i = 0; i < 6; i++) mbinit(sb + i * 8);
        asm volatile("fence.proxy.async.shared::cta;" ::: "memory");
    }
    __syncthreads();
    uint32_t tm;
    asm("ld.shared.b32 %0, [%1];" : "=r"(tm) : "r"(sb + 48));

    const char* a0 = (const char*)g_ah  + (size_t)((e * 24 + 2 * mb)     * 32) * TB;
    const char* a0l = (const char*)g_al + (size_t)((e * 24 + 2 * mb)     * 32) * TB;
    const char* a1 = (const char*)g_ah  + (size_t)((e * 24 + 2 * mb + 1) * 32) * TB;
    const char* a1l = (const char*)g_al + (size_t)((e * 24 + 2 * mb + 1) * 32) * TB;
    const char* b1 = (const char*)g_w1h + (size_t)((e * 16 + nb) * 32) * TB;
    const char* b1l = (const char*)g_w1l + (size_t)((e * 16 + nb) * 32) * TB;
    const char* b2 = (const char*)g_w2h + (size_t)((e * 16 + nb) * 32) * TB;
    const char* b2l = (const char*)g_w2l + (size_t)((e * 16 + nb) * 32) * TB;

    if (tid == 0) {
#pragma unroll
        for (int b = 0; b < 3; b++) {
            uint32_t st = sb + 1024 + b * 8 * TB, fb = sb + b * 8;
            expect_tx(fb, 8 * TB);
            size_t ko = (size_t)b * TB;
            bulkcp(st,          a0  + ko, fb); bulkcp(st + TB,     a0l + ko, fb);
            bulkcp(st + 2 * TB, a1  + ko, fb); bulkcp(st + 3 * TB, a1l + ko, fb);
            bulkcp(st + 4 * TB, b1  + ko, fb); bulkcp(st + 5 * TB, b1l + ko, fb);
            bulkcp(st + 6 * TB, b2  + ko, fb); bulkcp(st + 7 * TB, b2l + ko, fb);
        }
        for (int t = 0; t < 32; t++) {
            int slot = t % 3, ph = (t / 3) & 1;
            uint32_t st = sb + 1024 + slot * 8 * TB;
            mwait(sb + slot * 8, ph);
            uint64_t dA0 = sdesc(st),          dA0l = sdesc(st + TB);
            uint64_t dA1 = sdesc(st + 2 * TB), dA1l = sdesc(st + 3 * TB);
            uint64_t dB1 = sdesc(st + 4 * TB), dB1l = sdesc(st + 5 * TB);
            uint64_t dB2 = sdesc(st + 6 * TB), dB2l = sdesc(st + 7 * TB);
#pragma unroll
            for (int s = 0; s < 2; s++) {
                uint32_t en = (t | s) ? 1u : 0u;
                uint32_t o = s * 2;
                mma_ss(tm,       dA0 + o, dB1 + o, IDESC1, en);
                mma_ss(tm,       dA0 + o, dB1l + o, IDESC1, 1u);
                mma_ss(tm,       dA0l + o, dB1 + o, IDESC1, 1u);
                mma_ss(tm + 128, dA0 + o, dB2 + o, IDESC1, en);
                mma_ss(tm + 128, dA0 + o, dB2l + o, IDESC1, 1u);
                mma_ss(tm + 128, dA0l + o, dB2 + o, IDESC1, 1u);
                mma_ss(tm + 256, dA1 + o, dB1 + o, IDESC1, en);
                mma_ss(tm + 256, dA1 + o, dB1l + o, IDESC1, 1u);
                mma_ss(tm + 256, dA1l + o, dB1 + o, IDESC1, 1u);
                mma_ss(tm + 384, dA1 + o, dB2 + o, IDESC1, en);
                mma_ss(tm + 384, dA1 + o, dB2l + o, IDESC1, 1u);
                mma_ss(tm + 384, dA1l + o, dB2 + o, IDESC1, 1u);
            }
            commit_to(sb + 24 + slot * 8);
            mwait(sb + 24 + slot * 8, ph);
            if (t + 3 < 32) {
                uint32_t fb = sb + slot * 8;
                expect_tx(fb, 8 * TB);
                size_t ko = (size_t)(t + 3) * TB;
                bulkcp(st,          a0  + ko, fb); bulkcp(st + TB,     a0l + ko, fb);
                bulkcp(st + 2 * TB, a1  + ko, fb); bulkcp(st + 3 * TB, a1l + ko, fb);
                bulkcp(st + 4 * TB, b1  + ko, fb); bulkcp(st + 5 * TB, b1l + ko, fb);
                bulkcp(st + 6 * TB, b2  + ko, fb); bulkcp(st + 7 * TB, b2l + ko, fb);
            }
        }
    }
    __syncthreads();
    asm volatile("tcgen05.fence::after_thread_sync;" ::: "memory");

    // epilogue: silu(gate)*value -> SW64 hidden tiles. warps 0-3: m-half0, 4-7: m-half1
    {
        int mh = tid >> 7, row = tid & 127;
        uint32_t base = tm + mh * 256;
        int m128 = 2 * mb + mh;
#pragma unroll 1
        for (int c = 0; c < 4; c++) {
            uint32_t gg[32], vv[32];
            LDTM32(gg, base + c * 32);
            LDTM32(vv, base + 128 + c * 32);
            asm volatile("tcgen05.wait::ld.sync.aligned;" ::: "memory");
            uint32_t hbuf[16], lbuf[16];
#pragma unroll
            for (int j = 0; j < 16; j++) {
                float g0 = __uint_as_float(gg[2 * j]),     v0 = __uint_as_float(vv[2 * j]);
                float g1 = __uint_as_float(gg[2 * j + 1]), v1 = __uint_as_float(vv[2 * j + 1]);
                float h0 = g0 / (1.0f + __expf(-g0)) * v0;
                float h1 = g1 / (1.0f + __expf(-g1)) * v1;
                float f0 = __bfloat162float(__float2bfloat16(h0));
                float f1 = __bfloat162float(__float2bfloat16(h1));
                hbuf[j] = pk(f1, f0);
                lbuf[j] = pk(h1 - f1, h0 - f0);
            }
            size_t tb = (size_t)((e * 24 + m128) * 64 + nb * 4 + c) * TB;
#pragma unroll
            for (int q = 0; q < 4; q++) {
                uint32_t off = swz64((uint32_t)row * 64 + q * 16);
                *(uint4*)((char*)g_hh + tb + off) =
                    make_uint4(hbuf[4 * q], hbuf[4 * q + 1], hbuf[4 * q + 2], hbuf[4 * q + 3]);
                *(uint4*)((char*)g_hl + tb + off) =
                    make_uint4(lbuf[4 * q], lbuf[4 * q + 1], lbuf[4 * q + 2], lbuf[4 * q + 3]);
            }
        }
    }
    __syncthreads();
    if ((tid >> 5) == 0) {
        asm volatile("tcgen05.relinquish_alloc_permit.cta_group::1.sync.aligned;");
        asm volatile("tcgen05.dealloc.cta_group::1.sync.aligned.b32 %0, %1;" :: "r"(tm), "r"(512));
    }
#endif
}

// ==================== GEMM2: M=256, N=256, K32 stages, 3-ring ====================
// stage: a0h a0l a1h a1l bh(n0) bh(n1) bl(n0) bl(n1). TMEM: m0@0(256 cols) m1@256
__global__ __launch_bounds__(256) void k_gemm2_tc(float* __restrict__ out) {
#if TC
    extern __shared__ char sm[];
    const int e = blockIdx.z, mb = blockIdx.y, nb = blockIdx.x;
    const int n0 = nb * 256;
    int cnt = min(g_cnt[e], CAP);
    if (mb * 256 >= cnt) return;
    const int tid = threadIdx.x;
    uint32_t sb = smem_u32(sm);
    if ((tid >> 5) == 0)
        asm volatile("tcgen05.alloc.cta_group::1.sync.aligned.shared::cta.b32 [%0], %1;"
                     :: "r"(sb + 48), "r"(512) : "memory");
    if (tid == 0) {
#pragma unroll
        for (int i = 0; i < 6; i++) mbinit(sb + i * 8);
        asm volatile("fence.proxy.async.shared::cta;" ::: "memory");
    }
    __syncthreads();
    uint32_t tm;
    asm("ld.shared.b32 %0, [%1];" : "=r"(tm) : "r"(sb + 48));

    const char* a0  = (const char*)g_hh + (size_t)((e * 24 + 2 * mb)     * 64) * TB;
    const char* a0l = (const char*)g_hl + (size_t)((e * 24 + 2 * mb)     * 64) * TB;
    const char* a1  = (const char*)g_hh + (size_t)((e * 24 + 2 * mb + 1) * 64) * TB;
    const char* a1l = (const char*)g_hl + (size_t)((e * 24 + 2 * mb + 1) * 64) * TB;
    const char* bn0  = (const char*)g_w3h + (size_t)((e * 8 + 2 * nb)     * 64) * TB;
    const char* bn1  = (const char*)g_w3h + (size_t)((e * 8 + 2 * nb + 1) * 64) * TB;
    const char* bn0l = (const char*)g_w3l + (size_t)((e * 8 + 2 * nb)     * 64) * TB;
    const char* bn1l = (const char*)g_w3l + (size_t)((e * 8 + 2 * nb + 1) * 64) * TB;

    if (tid == 0) {
#pragma unroll
        for (int b = 0; b < 3; b++) {
            uint32_t st = sb + 1024 + b * 8 * TB, fb = sb + b * 8;
            expect_tx(fb, 8 * TB);
            size_t ko = (size_t)b * TB;
            bulkcp(st,          a0  + ko, fb); bulkcp(st + TB,     a0l + ko, fb);
            bulkcp(st + 2 * TB, a1  + ko, fb); bulkcp(st + 3 * TB, a1l + ko, fb);
            bulkcp(st + 4 * TB, bn0 + ko, fb); bulkcp(st + 5 * TB, bn1 + ko, fb);
            bulkcp(st + 6 * TB, bn0l + ko, fb); bulkcp(st + 7 * TB, bn1l + ko, fb);
        }
        for (int t = 0; t < 64; t++) {
            int slot = t % 3, ph = (t / 3) & 1;
            uint32_t st = sb + 1024 + slot * 8 * TB;
            mwait(sb + slot * 8, ph);
            uint64_t dA0 = sdesc(st),          dA0l = sdesc(st + TB);
            uint64_t dA1 = sdesc(st + 2 * TB), dA1l = sdesc(st + 3 * TB);
            uint64_t dB  = sdesc(st + 4 * TB), dBl  = sdesc(st + 6 * TB);
#pragma unroll
            for (int s = 0; s < 2; s++) {
                uint32_t en = (t | s) ? 1u : 0u;
                uint32_t o = s * 2;
                mma_ss(tm,       dA0 + o, dB + o,  IDESC2, en);
                mma_ss(tm,       dA0 + o, dBl + o, IDESC2, 1u);
                mma_ss(tm,       dA0l + o, dB + o, IDESC2, 1u);
                mma_ss(tm + 256, dA1 + o, dB + o,  IDESC2, en);
                mma_ss(tm + 256, dA1 + o, dBl + o, IDESC2, 1u);
                mma_ss(tm + 256, dA1l + o, dB + o, IDESC2, 1u);
            }
            commit_to(sb + 24 + slot * 8);
            mwait(sb + 24 + slot * 8, ph);
            if (t + 3 < 64) {
                uint32_t fb = sb + slot * 8;
                expect_tx(fb, 8 * TB);
                size_t ko = (size_t)(t + 3) * TB;
                bulkcp(st,          a0  + ko, fb); bulkcp(st + TB,     a0l + ko, fb);
                bulkcp(st + 2 * TB, a1  + ko, fb); bulkcp(st + 3 * TB, a1l + ko, fb);
                bulkcp(st + 4 * TB, bn0 + ko, fb); bulkcp(st + 5 * TB, bn1 + ko, fb);
                bulkcp(st + 6 * TB, bn0l + ko, fb); bulkcp(st + 7 * TB, bn1l + ko, fb);
            }
        }
    }
    __syncthreads();
    asm volatile("tcgen05.fence::after_thread_sync;" ::: "memory");

    // epilogue: warps 0-3 -> m-half0 (cols 0-255), 4-7 -> m-half1 (cols 256-511)
    {
        int mh = tid >> 7;
        int row = mb * 256 + mh * 128 + (tid & 127);
        bool val = row < cnt;
        int tok = 0; float w = 0.0f;
        if (val) { tok = g_tok[e * CAP + row]; w = g_wt[e * CAP + row]; }
        uint32_t base = tm + mh * 256;
#pragma unroll 1
        for (int c = 0; c < 8; c++) {
            uint32_t dd[32];
            LDTM32(dd, base + c * 32);
            asm volatile("tcgen05.wait::ld.sync.aligned;" ::: "memory");
            if (val) {
                float* o = out + (size_t)tok * DM + n0 + c * 32;
#pragma unroll
                for (int j = 0; j < 16; j++)
                    red2(o + 2 * j, w * __uint_as_float(dd[2 * j]),
                                    w * __uint_as_float(dd[2 * j + 1]));
            }
        }
    }
    __syncthreads();
    if ((tid >> 5) == 0) {
        asm volatile("tcgen05.relinquish_alloc_permit.cta_group::1.sync.aligned;");
        asm volatile("tcgen05.dealloc.cta_group::1.sync.aligned.b32 %0, %1;" :: "r"(tm), "r"(512));
    }
#endif
}

// ---- launch ----
extern "C" void kernel_launch(void* const* d_in, const int* in_sizes, int n_in,
                              void* d_out, int out_size) {
    const float* x   = (const float*)d_in[0];
    const int*   idx = (const int*)  d_in[1];
    const float* ew  = (const float*)d_in[2];
    const float* w1  = (const float*)d_in[3];
    const float* w2  = (const float*)d_in[4];
    const float* w3  = (const float*)d_in[5];
    float* out = (float*)d_out;

    const int SMB = 1024 + 24 * (int)TB;  // 197632
    cudaFuncSetAttribute(k_gemm1_tc, cudaFuncAttributeMaxDynamicSharedMemorySize, SMB);
    cudaFuncSetAttribute(k_gemm2_tc, cudaFuncAttributeMaxDynamicSharedMemorySize, SMB);

    cudaMemsetAsync(out, 0, (size_t)out_size * sizeof(float));
    k_zero<<<1, 32>>>();
    k_dispatch<<<(NT * TK + 255) / 256, 256>>>(idx, ew);
    k_gather<<<dim3(CAP, NE), 256>>>(x);
    k_transw<<<dim3(DF / 32, DM / 32, NE), 256>>>(w1, 0, DM, DF);
    k_transw<<<dim3(DF / 32, DM / 32, NE), 256>>>(w2, 1, DM, DF);
    k_transw<<<dim3(DM / 32, DF / 32, NE), 256>>>(w3, 2, DF, DM);

    k_gemm1_tc<<<dim3(DF / 128, CAP / 256, NE), 256, SMB>>>();
    k_gemm2_tc<<<dim3(DM / 256, CAP / 256, NE), 256, SMB>>>(out);
}

// round 15
// speedup vs baseline: 1.2709x; 1.2709x over previous
#include <cuda_runtime.h>
#include <cuda_bf16.h>
#include <stdint.h>

#define NT 8192
#define TK 2
#define NE 8
#define DM 1024
#define DF 2048
#define CAP 3072
#define TB 8192u            // tile bytes: 128 rows x 32 K-cols bf16, SW64-swizzled
#define IDESC1 0x8200490u   // kind::f16: F32 acc, bf16 A/B, M=128, N=128
#define IDESC2 0x8400490u   // N=256 variant

#if defined(__CUDA_ARCH__) && (__CUDA_ARCH__ >= 1000) && \
    (defined(__CUDA_ARCH_FEAT_SM103_ALL) || defined(__CUDA_ARCH_FEAT_SM100_ALL) || \
     defined(__CUDA_ARCH_FEAT_SM101_ALL) || defined(__CUDA_ARCH_SPECIFIC__) || \
     defined(__CUDA_ARCH_FAMILY_SPECIFIC__))
#define TC 1
#else
#define TC 0
#endif

// ---- persistent scratch (8KB SW64 tiles) ----
// A: ((e*24+m128)*32+k32)   W1/W2: ((e*16+n128)*32+k32)
// W3: ((e*8+n128)*64+k32)   H: ((e*24+m128)*64+f32)
__device__ int   g_cnt[NE];
__device__ int   g_tok[NE * CAP];
__device__ float g_wt[NE * CAP];
__device__ __align__(128) __nv_bfloat16 g_ah[(size_t)NE*CAP*DM], g_al[(size_t)NE*CAP*DM];
__device__ __align__(128) __nv_bfloat16 g_w1h[(size_t)NE*DF*DM], g_w1l[(size_t)NE*DF*DM];
__device__ __align__(128) __nv_bfloat16 g_w2h[(size_t)NE*DF*DM], g_w2l[(size_t)NE*DF*DM];
__device__ __align__(128) __nv_bfloat16 g_w3h[(size_t)NE*DM*DF], g_w3l[(size_t)NE*DM*DF];
__device__ __align__(128) __nv_bfloat16 g_hh[(size_t)NE*CAP*DF], g_hl[(size_t)NE*CAP*DF];

// ---- helpers ----
__device__ __forceinline__ uint32_t smem_u32(const void* p) {
    uint32_t a;
    asm("{ .reg .u64 t; cvta.to.shared.u64 t, %1; cvt.u32.u64 %0, t; }" : "=r"(a) : "l"(p));
    return a;
}
__device__ __forceinline__ uint32_t pk(float hi, float lo) {
    uint32_t r; asm("cvt.rn.bf16x2.f32 %0, %1, %2;" : "=r"(r) : "f"(hi), "f"(lo)); return r;
}
__device__ __forceinline__ void red2(float* p, float a, float b) {
    asm volatile("red.global.add.v2.f32 [%0], {%1, %2};" :: "l"(p), "f"(a), "f"(b) : "memory");
}
__device__ __forceinline__ uint32_t swz64(uint32_t o) { return o ^ ((o >> 3) & 0x30); }

#if TC
__device__ __forceinline__ uint64_t sdesc(uint32_t a) {  // K-major SW64: LBO=1, SBO=32
    return ((uint64_t)4 << 61) | ((uint64_t)1 << 46) | ((uint64_t)32 << 32) |
           ((uint64_t)1 << 16) | ((a >> 4) & 0x3FFF);
}
__device__ __forceinline__ void mma_ss(uint32_t d, uint64_t ad, uint64_t bd,
                                       uint32_t idesc, uint32_t en) {
    asm volatile(
        "{\n\t.reg .pred p;\n\tsetp.ne.u32 p, %4, 0;\n\t"
        "tcgen05.mma.cta_group::1.kind::f16 [%0], %1, %2, %3, {%5, %5, %5, %5}, p;\n\t}"
        :: "r"(d), "l"(ad), "l"(bd), "r"(idesc), "r"(en), "r"(0u) : "memory");
}
__device__ __forceinline__ void mwait(uint32_t mbar, int phase) {
    asm volatile(
        "{\n\t.reg .pred P;\n\tWL%=:\n\t"
        "mbarrier.try_wait.parity.acquire.cta.shared::cta.b64 P, [%0], %1, 0x989680;\n\t"
        "@P bra.uni WD%=;\n\tbra.uni WL%=;\n\tWD%=:\n\t}"
        :: "r"(mbar), "r"((uint32_t)phase) : "memory");
}
__device__ __forceinline__ void bulkcp(uint32_t dst, const void* src, uint32_t mbar) {
    asm volatile(
        "cp.async.bulk.shared::cluster.global.mbarrier::complete_tx::bytes [%0], [%1], %2, [%3];"
        :: "r"(dst), "l"(src), "r"(TB), "r"(mbar) : "memory");
}
__device__ __forceinline__ void expect_tx(uint32_t mbar, uint32_t bytes) {
    asm volatile("mbarrier.arrive.expect_tx.shared.b64 _, [%0], %1;"
                 :: "r"(mbar), "r"(bytes) : "memory");
}
__device__ __forceinline__ void mbinit(uint32_t mbar) {
    asm volatile("mbarrier.init.shared.b64 [%0], 1;" :: "r"(mbar) : "memory");
}
__device__ __forceinline__ void commit_to(uint32_t mbar) {
    asm volatile("tcgen05.commit.cta_group::1.mbarrier::arrive::one.shared::cluster.b64 [%0];"
                 :: "r"(mbar) : "memory");
}
#define LDTM32(r, addr) \
    asm volatile("tcgen05.ld.sync.aligned.32x32b.x32.b32 " \
        "{%0,%1,%2,%3,%4,%5,%6,%7,%8,%9,%10,%11,%12,%13,%14,%15," \
        "%16,%17,%18,%19,%20,%21,%22,%23,%24,%25,%26,%27,%28,%29,%30,%31}, [%32];" \
        : "=r"((r)[0]),"=r"((r)[1]),"=r"((r)[2]),"=r"((r)[3]),"=r"((r)[4]),"=r"((r)[5]), \
          "=r"((r)[6]),"=r"((r)[7]),"=r"((r)[8]),"=r"((r)[9]),"=r"((r)[10]),"=r"((r)[11]), \
          "=r"((r)[12]),"=r"((r)[13]),"=r"((r)[14]),"=r"((r)[15]),"=r"((r)[16]),"=r"((r)[17]), \
          "=r"((r)[18]),"=r"((r)[19]),"=r"((r)[20]),"=r"((r)[21]),"=r"((r)[22]),"=r"((r)[23]), \
          "=r"((r)[24]),"=r"((r)[25]),"=r"((r)[26]),"=r"((r)[27]),"=r"((r)[28]),"=r"((r)[29]), \
          "=r"((r)[30]),"=r"((r)[31]) : "r"(addr))
#endif  // TC

// ---- dispatch / prep ----
__global__ void k_zero() { if (threadIdx.x < NE) g_cnt[threadIdx.x] = 0; }

__global__ void k_dispatch(const int* __restrict__ idx, const float* __restrict__ w) {
    int i = blockIdx.x * blockDim.x + threadIdx.x;
    if (i >= NT * TK) return;
    int e = idx[i];
    int p = atomicAdd(&g_cnt[e], 1);
    if (p < CAP) { g_tok[e * CAP + p] = i >> 1; g_wt[e * CAP + p] = w[i]; }
}

__global__ void k_gather(const float* __restrict__ x) {
    int e = blockIdx.y, r = blockIdx.x;
    if (r >= min(g_cnt[e], CAP)) return;
    int t = g_tok[e * CAP + r];
    int d = threadIdx.x * 4;
    float4 v = *(const float4*)(x + (size_t)t * DM + d);
    float f0 = __bfloat162float(__float2bfloat16(v.x));
    float f1 = __bfloat162float(__float2bfloat16(v.y));
    float f2 = __bfloat162float(__float2bfloat16(v.z));
    float f3 = __bfloat162float(__float2bfloat16(v.w));
    size_t tile = (size_t)((e * 24 + (r >> 7)) * 32 + (d >> 5)) * TB;
    uint32_t off = swz64((uint32_t)(r & 127) * 64 + (d & 31) * 2);
    *(uint2*)((char*)g_ah + tile + off) = make_uint2(pk(f1, f0), pk(f3, f2));
    *(uint2*)((char*)g_al + tile + off) = make_uint2(pk(v.y - f1, v.x - f0), pk(v.w - f3, v.z - f2));
}

// transpose + split: src [E][K][N] f32 -> SW64 tiles [E][n128][k32]
__global__ __launch_bounds__(256) void k_transw(const float* __restrict__ src,
                                                int which, int K, int N) {
    __shared__ float ts[32][33];
    __nv_bfloat16 *dh, *dl;
    if (which == 0)      { dh = g_w1h; dl = g_w1l; }
    else if (which == 1) { dh = g_w2h; dl = g_w2l; }
    else                 { dh = g_w3h; dl = g_w3l; }
    const int KB = K / 32;
    int e = blockIdx.z, n0 = blockIdx.x * 32, k0 = blockIdx.y * 32;
    int tx = threadIdx.x & 31, ty = threadIdx.x >> 5;
    const float* s = src + (size_t)e * K * N;
#pragma unroll
    for (int j = 0; j < 4; j++) ts[ty + 8 * j][tx] = s[(size_t)(k0 + ty + 8 * j) * N + n0 + tx];
    __syncthreads();
    int tilesPerE = (N / 128) * KB;
#pragma unroll
    for (int j = 0; j < 4; j++) {
        int n = n0 + ty + 8 * j, k = k0 + tx;
        float v = ts[tx][ty + 8 * j];
        size_t tile = (size_t)(e * tilesPerE + (n >> 7) * KB + (k >> 5)) * TB;
        uint32_t off = swz64((uint32_t)(n & 127) * 64 + (k & 31) * 2);
        __nv_bfloat16 h = __float2bfloat16(v);
        *(__nv_bfloat16*)((char*)dh + tile + off) = h;
        *(__nv_bfloat16*)((char*)dl + tile + off) = __float2bfloat16(v - __bfloat162float(h));
    }
}

// ==================== GEMM1: M=256, N=128, warp-specialized pipeline ====================
// smem: full[3]@+0/8/16  done[3]@+24/32/40  final@+48  tmem_ptr@+56  stages@+1024 (3 x 8 x 8KB)
// TMEM: gm0@0 vm0@128 gm1@256 vm1@384
__global__ __launch_bounds__(256) void k_gemm1_tc() {
#if TC
    extern __shared__ char sm[];
    const int e = blockIdx.z, mb = blockIdx.y, nb = blockIdx.x;
    int cnt = min(g_cnt[e], CAP);
    if (mb * 256 >= cnt) return;
    const int tid = threadIdx.x;
    uint32_t sb = smem_u32(sm);
    if ((tid >> 5) == 0)
        asm volatile("tcgen05.alloc.cta_group::1.sync.aligned.shared::cta.b32 [%0], %1;"
                     :: "r"(sb + 56), "r"(512) : "memory");
    if (tid == 0) {
#pragma unroll
        for (int i = 0; i < 7; i++) mbinit(sb + i * 8);
        asm volatile("fence.proxy.async.shared::cta;" ::: "memory");
    }
    __syncthreads();
    uint32_t tm;
    asm("ld.shared.b32 %0, [%1];" : "=r"(tm) : "r"(sb + 56));

    const char* a0 = (const char*)g_ah  + (size_t)((e * 24 + 2 * mb)     * 32) * TB;
    const char* a0l = (const char*)g_al + (size_t)((e * 24 + 2 * mb)     * 32) * TB;
    const char* a1 = (const char*)g_ah  + (size_t)((e * 24 + 2 * mb + 1) * 32) * TB;
    const char* a1l = (const char*)g_al + (size_t)((e * 24 + 2 * mb + 1) * 32) * TB;
    const char* b1 = (const char*)g_w1h + (size_t)((e * 16 + nb) * 32) * TB;
    const char* b1l = (const char*)g_w1l + (size_t)((e * 16 + nb) * 32) * TB;
    const char* b2 = (const char*)g_w2h + (size_t)((e * 16 + nb) * 32) * TB;
    const char* b2l = (const char*)g_w2l + (size_t)((e * 16 + nb) * 32) * TB;

    if (tid == 32) {
        // ---- copy producer warp ----
#pragma unroll
        for (int b = 0; b < 3; b++) {
            uint32_t st = sb + 1024 + b * 8 * TB, fb = sb + b * 8;
            expect_tx(fb, 8 * TB);
            size_t ko = (size_t)b * TB;
            bulkcp(st,          a0  + ko, fb); bulkcp(st + TB,     a0l + ko, fb);
            bulkcp(st + 2 * TB, a1  + ko, fb); bulkcp(st + 3 * TB, a1l + ko, fb);
            bulkcp(st + 4 * TB, b1  + ko, fb); bulkcp(st + 5 * TB, b1l + ko, fb);
            bulkcp(st + 6 * TB, b2  + ko, fb); bulkcp(st + 7 * TB, b2l + ko, fb);
        }
        for (int u = 3; u < 32; u++) {
            int slot = u % 3;
            mwait(sb + 24 + slot * 8, ((u - 3) / 3) & 1);   // stage u-3's MMAs done
            uint32_t st = sb + 1024 + slot * 8 * TB, fb = sb + slot * 8;
            expect_tx(fb, 8 * TB);
            size_t ko = (size_t)u * TB;
            bulkcp(st,          a0  + ko, fb); bulkcp(st + TB,     a0l + ko, fb);
            bulkcp(st + 2 * TB, a1  + ko, fb); bulkcp(st + 3 * TB, a1l + ko, fb);
            bulkcp(st + 4 * TB, b1  + ko, fb); bulkcp(st + 5 * TB, b1l + ko, fb);
            bulkcp(st + 6 * TB, b2  + ko, fb); bulkcp(st + 7 * TB, b2l + ko, fb);
        }
    } else if (tid == 0) {
        // ---- MMA issuer warp: never waits for MMA completion ----
        for (int t = 0; t < 32; t++) {
            int slot = t % 3;
            mwait(sb + slot * 8, (t / 3) & 1);
            uint32_t st = sb + 1024 + slot * 8 * TB;
            uint64_t dA0 = sdesc(st),          dA0l = sdesc(st + TB);
            uint64_t dA1 = sdesc(st + 2 * TB), dA1l = sdesc(st + 3 * TB);
            uint64_t dB1 = sdesc(st + 4 * TB), dB1l = sdesc(st + 5 * TB);
            uint64_t dB2 = sdesc(st + 6 * TB), dB2l = sdesc(st + 7 * TB);
#pragma unroll
            for (int s = 0; s < 2; s++) {
                uint32_t en = (t | s) ? 1u : 0u;
                uint32_t o = s * 2;
                mma_ss(tm,       dA0 + o, dB1 + o, IDESC1, en);
                mma_ss(tm,       dA0 + o, dB1l + o, IDESC1, 1u);
                mma_ss(tm,       dA0l + o, dB1 + o, IDESC1, 1u);
                mma_ss(tm + 128, dA0 + o, dB2 + o, IDESC1, en);
                mma_ss(tm + 128, dA0 + o, dB2l + o, IDESC1, 1u);
                mma_ss(tm + 128, dA0l + o, dB2 + o, IDESC1, 1u);
                mma_ss(tm + 256, dA1 + o, dB1 + o, IDESC1, en);
                mma_ss(tm + 256, dA1 + o, dB1l + o, IDESC1, 1u);
                mma_ss(tm + 256, dA1l + o, dB1 + o, IDESC1, 1u);
                mma_ss(tm + 384, dA1 + o, dB2 + o, IDESC1, en);
                mma_ss(tm + 384, dA1 + o, dB2l + o, IDESC1, 1u);
                mma_ss(tm + 384, dA1l + o, dB2 + o, IDESC1, 1u);
            }
            commit_to(sb + 24 + slot * 8);
        }
        commit_to(sb + 48);   // covers all prior MMAs -> final barrier
    }
    mwait(sb + 48, 0);        // everyone waits for all MMAs complete
    asm volatile("tcgen05.fence::after_thread_sync;" ::: "memory");

    // epilogue: silu(gate)*value -> SW64 hidden tiles. warps 0-3: m-half0, 4-7: m-half1
    {
        int mh = tid >> 7, row = tid & 127;
        uint32_t base = tm + mh * 256;
        int m128 = 2 * mb + mh;
#pragma unroll 1
        for (int c = 0; c < 4; c++) {
            uint32_t gg[32], vv[32];
            LDTM32(gg, base + c * 32);
            LDTM32(vv, base + 128 + c * 32);
            asm volatile("tcgen05.wait::ld.sync.aligned;" ::: "memory");
            uint32_t hbuf[16], lbuf[16];
#pragma unroll
            for (int j = 0; j < 16; j++) {
                float g0 = __uint_as_float(gg[2 * j]),     v0 = __uint_as_float(vv[2 * j]);
                float g1 = __uint_as_float(gg[2 * j + 1]), v1 = __uint_as_float(vv[2 * j + 1]);
                float h0 = g0 / (1.0f + __expf(-g0)) * v0;
                float h1 = g1 / (1.0f + __expf(-g1)) * v1;
                float f0 = __bfloat162float(__float2bfloat16(h0));
                float f1 = __bfloat162float(__float2bfloat16(h1));
                hbuf[j] = pk(f1, f0);
                lbuf[j] = pk(h1 - f1, h0 - f0);
            }
            size_t tb = (size_t)((e * 24 + m128) * 64 + nb * 4 + c) * TB;
#pragma unroll
            for (int q = 0; q < 4; q++) {
                uint32_t off = swz64((uint32_t)row * 64 + q * 16);
                *(uint4*)((char*)g_hh + tb + off) =
                    make_uint4(hbuf[4 * q], hbuf[4 * q + 1], hbuf[4 * q + 2], hbuf[4 * q + 3]);
                *(uint4*)((char*)g_hl + tb + off) =
                    make_uint4(lbuf[4 * q], lbuf[4 * q + 1], lbuf[4 * q + 2], lbuf[4 * q + 3]);
            }
        }
    }
    __syncthreads();
    if ((tid >> 5) == 0) {
        asm volatile("tcgen05.relinquish_alloc_permit.cta_group::1.sync.aligned;");
        asm volatile("tcgen05.dealloc.cta_group::1.sync.aligned.b32 %0, %1;" :: "r"(tm), "r"(512));
    }
#endif
}

// ==================== GEMM2: M=256, N=256, warp-specialized pipeline ====================
__global__ __launch_bounds__(256) void k_gemm2_tc(float* __restrict__ out) {
#if TC
    extern __shared__ char sm[];
    const int e = blockIdx.z, mb = blockIdx.y, nb = blockIdx.x;
    const int n0 = nb * 256;
    int cnt = min(g_cnt[e], CAP);
    if (mb * 256 >= cnt) return;
    const int tid = threadIdx.x;
    uint32_t sb = smem_u32(sm);
    if ((tid >> 5) == 0)
        asm volatile("tcgen05.alloc.cta_group::1.sync.aligned.shared::cta.b32 [%0], %1;"
                     :: "r"(sb + 56), "r"(512) : "memory");
    if (tid == 0) {
#pragma unroll
        for (int i = 0; i < 7; i++) mbinit(sb + i * 8);
        asm volatile("fence.proxy.async.shared::cta;" ::: "memory");
    }
    __syncthreads();
    uint32_t tm;
    asm("ld.shared.b32 %0, [%1];" : "=r"(tm) : "r"(sb + 56));

    const char* a0  = (const char*)g_hh + (size_t)((e * 24 + 2 * mb)     * 64) * TB;
    const char* a0l = (const char*)g_hl + (size_t)((e * 24 + 2 * mb)     * 64) * TB;
    const char* a1  = (const char*)g_hh + (size_t)((e * 24 + 2 * mb + 1) * 64) * TB;
    const char* a1l = (const char*)g_hl + (size_t)((e * 24 + 2 * mb + 1) * 64) * TB;
    const char* bn0  = (const char*)g_w3h + (size_t)((e * 8 + 2 * nb)     * 64) * TB;
    const char* bn1  = (const char*)g_w3h + (size_t)((e * 8 + 2 * nb + 1) * 64) * TB;
    const char* bn0l = (const char*)g_w3l + (size_t)((e * 8 + 2 * nb)     * 64) * TB;
    const char* bn1l = (const char*)g_w3l + (size_t)((e * 8 + 2 * nb + 1) * 64) * TB;

    if (tid == 32) {
#pragma unroll
        for (int b = 0; b < 3; b++) {
            uint32_t st = sb + 1024 + b * 8 * TB, fb = sb + b * 8;
            expect_tx(fb, 8 * TB);
            size_t ko = (size_t)b * TB;
            bulkcp(st,          a0  + ko, fb); bulkcp(st + TB,     a0l + ko, fb);
            bulkcp(st + 2 * TB, a1  + ko, fb); bulkcp(st + 3 * TB, a1l + ko, fb);
            bulkcp(st + 4 * TB, bn0 + ko, fb); bulkcp(st + 5 * TB, bn1 + ko, fb);
            bulkcp(st + 6 * TB, bn0l + ko, fb); bulkcp(st + 7 * TB, bn1l + ko, fb);
        }
        for (int u = 3; u < 64; u++) {
            int slot = u % 3;
            mwait(sb + 24 + slot * 8, ((u - 3) / 3) & 1);
            uint32_t st = sb + 1024 + slot * 8 * TB, fb = sb + slot * 8;
            expect_tx(fb, 8 * TB);
            size_t ko = (size_t)u * TB;
            bulkcp(st,          a0  + ko, fb); bulkcp(st + TB,     a0l + ko, fb);
            bulkcp(st + 2 * TB, a1  + ko, fb); bulkcp(st + 3 * TB, a1l + ko, fb);
            bulkcp(st + 4 * TB, bn0 + ko, fb); bulkcp(st + 5 * TB, bn1 + ko, fb);
            bulkcp(st + 6 * TB, bn0l + ko, fb); bulkcp(st + 7 * TB, bn1l + ko, fb);
        }
    } else if (tid == 0) {
        for (int t = 0; t < 64; t++) {
            int slot = t % 3;
            mwait(sb + slot * 8, (t / 3) & 1);
            uint32_t st = sb + 1024 + slot * 8 * TB;
            uint64_t dA0 = sdesc(st),          dA0l = sdesc(st + TB);
            uint64_t dA1 = sdesc(st + 2 * TB), dA1l = sdesc(st + 3 * TB);
            uint64_t dB  = sdesc(st + 4 * TB), dBl  = sdesc(st + 6 * TB);
#pragma unroll
            for (int s = 0; s < 2; s++) {
                uint32_t en = (t | s) ? 1u : 0u;
                uint32_t o = s * 2;
                mma_ss(tm,       dA0 + o, dB + o,  IDESC2, en);
                mma_ss(tm,       dA0 + o, dBl + o, IDESC2, 1u);
                mma_ss(tm,       dA0l + o, dB + o, IDESC2, 1u);
                mma_ss(tm + 256, dA1 + o, dB + o,  IDESC2, en);
                mma_ss(tm + 256, dA1 + o, dBl + o, IDESC2, 1u);
                mma_ss(tm + 256, dA1l + o, dB + o, IDESC2, 1u);
            }
            commit_to(sb + 24 + slot * 8);
        }
        commit_to(sb + 48);
    }
    mwait(sb + 48, 0);
    asm volatile("tcgen05.fence::after_thread_sync;" ::: "memory");

    // epilogue: warps 0-3 -> m-half0 (cols 0-255), 4-7 -> m-half1 (cols 256-511)
    {
        int mh = tid >> 7;
        int row = mb * 256 + mh * 128 + (tid & 127);
        bool val = row < cnt;
        int tok = 0; float w = 0.0f;
        if (val) { tok = g_tok[e * CAP + row]; w = g_wt[e * CAP + row]; }
        uint32_t base = tm + mh * 256;
#pragma unroll 1
        for (int c = 0; c < 8; c++) {
            uint32_t dd[32];
            LDTM32(dd, base + c * 32);
            asm volatile("tcgen05.wait::ld.sync.aligned;" ::: "memory");
            if (val) {
                float* o = out + (size_t)tok * DM + n0 + c * 32;
#pragma unroll
                for (int j = 0; j < 16; j++)
                    red2(o + 2 * j, w * __uint_as_float(dd[2 * j]),
                                    w * __uint_as_float(dd[2 * j + 1]));
            }
        }
    }
    __syncthreads();
    if ((tid >> 5) == 0) {
        asm volatile("tcgen05.relinquish_alloc_permit.cta_group::1.sync.aligned;");
        asm volatile("tcgen05.dealloc.cta_group::1.sync.aligned.b32 %0, %1;" :: "r"(tm), "r"(512));
    }
#endif
}

// ---- launch ----
extern "C" void kernel_launch(void* const* d_in, const int* in_sizes, int n_in,
                              void* d_out, int out_size) {
    const float* x   = (const float*)d_in[0];
    const int*   idx = (const int*)  d_in[1];
    const float* ew  = (const float*)d_in[2];
    const float* w1  = (const float*)d_in[3];
    const float* w2  = (const float*)d_in[4];
    const float* w3  = (const float*)d_in[5];
    float* out = (float*)d_out;

    const int SMB = 1024 + 24 * (int)TB;  // 197632
    cudaFuncSetAttribute(k_gemm1_tc, cudaFuncAttributeMaxDynamicSharedMemorySize, SMB);
    cudaFuncSetAttribute(k_gemm2_tc, cudaFuncAttributeMaxDynamicSharedMemorySize, SMB);

    cudaMemsetAsync(out, 0, (size_t)out_size * sizeof(float));
    k_zero<<<1, 32>>>();
    k_dispatch<<<(NT * TK + 255) / 256, 256>>>(idx, ew);
    k_gather<<<dim3(CAP, NE), 256>>>(x);
    k_transw<<<dim3(DF / 32, DM / 32, NE), 256>>>(w1, 0, DM, DF);
    k_transw<<<dim3(DF / 32, DM / 32, NE), 256>>>(w2, 1, DM, DF);
    k_transw<<<dim3(DM / 32, DF / 32, NE), 256>>>(w3, 2, DF, DM);

    k_gemm1_tc<<<dim3(DF / 128, CAP / 256, NE), 256, SMB>>>();
    k_gemm2_tc<<<dim3(DM / 256, CAP / 256, NE), 256, SMB>>>(out);
}